// round 5
// baseline (speedup 1.0000x reference)
#include <cuda_runtime.h>
#include <cuda_bf16.h>
#include <stdint.h>
#include <math.h>

#define NODES 50000
#define EDGES 600000
#define DIN 128
#define DHID 256

// ---------------- device scratch (static, no allocation) ----------------
__device__ int   g_cnt[NODES];
__device__ int   g_off[NODES];
__device__ int   g_cur[NODES];
__device__ int   g_csrc[EDGES];
__device__ __align__(16) float g_agg1[NODES * DIN];
__device__ float2 g_t12[NODES];
__device__ float2 g_w12[NODES];
__device__ float4 g_P[DHID];
__device__ float  g_c[2];
__device__ float2 g_s[NODES];

// ---------------- zero the histogram ----------------
__global__ void k_zero() {
    int i = blockIdx.x * blockDim.x + threadIdx.x;
    if (i < NODES) g_cnt[i] = 0;
}

// ---------------- histogram of dst ----------------
__global__ void k_hist(const int* __restrict__ dst, int E) {
    int e = blockIdx.x * blockDim.x + threadIdx.x;
    if (e < E) atomicAdd(&g_cnt[dst[e]], 1);
}

// ---------------- single-block exclusive scan over 50K counts ----------------
__global__ void __launch_bounds__(1024) k_scan() {
    __shared__ int part[1024];
    const int t = threadIdx.x;
    const int per = (NODES + 1023) / 1024;
    const int base = t * per;

    int sum = 0;
    for (int i = 0; i < per; i++) {
        int n = base + i;
        if (n < NODES) sum += g_cnt[n];
    }
    part[t] = sum;
    __syncthreads();
    for (int off = 1; off < 1024; off <<= 1) {
        int u = (t >= off) ? part[t - off] : 0;
        __syncthreads();
        part[t] += u;
        __syncthreads();
    }
    int run = part[t] - sum;
    for (int i = 0; i < per; i++) {
        int n = base + i;
        if (n < NODES) {
            g_off[n] = run;
            g_cur[n] = run;
            run += g_cnt[n];
        }
    }
}

// ---------------- CSR fill ----------------
__global__ void k_fill(const int* __restrict__ src,
                       const int* __restrict__ dst, int E) {
    int e = blockIdx.x * blockDim.x + threadIdx.x;
    if (e >= E) return;
    int d = dst[e];
    int pos = atomicAdd(&g_cur[d], 1);
    g_csrc[pos] = src[e];
}

// ---------------- layer-1 mean aggregate: one warp per node, pure gather ----
__global__ void __launch_bounds__(256) k_agg1(const float* __restrict__ x) {
    int n = blockIdx.x * 8 + (threadIdx.x >> 5);
    if (n >= NODES) return;
    int lane = threadIdx.x & 31;
    int start = g_off[n], cnt = g_cnt[n];

    float4 acc = make_float4(0.f, 0.f, 0.f, 0.f);
    int j = 0;
    for (; j + 2 <= cnt; j += 2) {
        int s0 = g_csrc[start + j];
        int s1 = g_csrc[start + j + 1];
        float4 v0 = ((const float4*)(x + (size_t)s0 * DIN))[lane];
        float4 v1 = ((const float4*)(x + (size_t)s1 * DIN))[lane];
        acc.x += v0.x + v1.x; acc.y += v0.y + v1.y;
        acc.z += v0.z + v1.z; acc.w += v0.w + v1.w;
    }
    if (j < cnt) {
        int s0 = g_csrc[start + j];
        float4 v0 = ((const float4*)(x + (size_t)s0 * DIN))[lane];
        acc.x += v0.x; acc.y += v0.y; acc.z += v0.z; acc.w += v0.w;
    }
    float r = 1.0f / fmaxf((float)cnt, 1.0f);
    acc.x *= r; acc.y *= r; acc.z *= r; acc.w *= r;
    ((float4*)(g_agg1 + (size_t)n * DIN))[lane] = acc;
}

// -------- fold layer 2 + link head into 4 projection vectors --------
__global__ void k_prep(const float* __restrict__ W2l, const float* __restrict__ W2r,
                       const float* __restrict__ Wlin, const float* __restrict__ b2l)
{
    int j = threadIdx.x;
    float u1 = 0.f, u2 = 0.f, v1 = 0.f, v2 = 0.f;
    for (int k = 0; k < DIN; k++) {
        float wa = Wlin[k], wb = Wlin[DIN + k];
        float l = W2l[j * DIN + k], r = W2r[j * DIN + k];
        u1 = fmaf(l, wa, u1); u2 = fmaf(l, wb, u2);
        v1 = fmaf(r, wa, v1); v2 = fmaf(r, wb, v2);
    }
    g_P[j] = make_float4(u1, u2, v1, v2);
    if (j == 0) {
        float c1 = 0.f, c2 = 0.f;
        for (int k = 0; k < DIN; k++) {
            c1 = fmaf(b2l[k], Wlin[k], c1);
            c2 = fmaf(b2l[k], Wlin[DIN + k], c2);
        }
        g_c[0] = c1; g_c[1] = c2;
    }
}

// ====================== tensor-core layer-1 GEMM =========================
// D[64,256] = [agg1|x](64x256) @ [W1l;W1r](256x256), bf16 2-term split
// (3 mma passes: hi*hi + hi*lo + lo*hi), fp32 accum. Then fused
// bias+relu+projection epilogue.
#define SA_STRIDE 264                 // 256 + 8 pad (conflict-free A frags)
#define SB_STRIDE 40                  // 32 + 8 pad (conflict-free B frags)

#define MMA_BF16(d, a, b0_, b1_)                                             \
    asm volatile("mma.sync.aligned.m16n8k16.row.col.f32.bf16.bf16.f32 "     \
        "{%0,%1,%2,%3}, {%4,%5,%6,%7}, {%8,%9}, {%0,%1,%2,%3};"             \
        : "+f"(d[0]), "+f"(d[1]), "+f"(d[2]), "+f"(d[3])                    \
        : "r"(a[0]), "r"(a[1]), "r"(a[2]), "r"(a[3]), "r"(b0_), "r"(b1_))

__global__ void __launch_bounds__(256, 1) k_l1(
    const float* __restrict__ x,
    const float* __restrict__ W1l, const float* __restrict__ W1r,
    const float* __restrict__ b1l)
{
    extern __shared__ char smraw[];
    __nv_bfloat16* sah = (__nv_bfloat16*)smraw;          // 64 x SA_STRIDE
    __nv_bfloat16* sal = sah + 64 * SA_STRIDE;
    __nv_bfloat16* sbh = sal + 64 * SA_STRIDE;           // 256 x SB_STRIDE ([n][k])
    __nv_bfloat16* sbl = sbh + 256 * SB_STRIDE;
    float4* spart = (float4*)(sbl + 256 * SB_STRIDE);    // [4][64]

    const int tid = threadIdx.x;
    const int node0 = blockIdx.x * 64;

    // ---- stage A (hi/lo split): cols 0..127 = agg1, 128..255 = x ----
    for (int i = tid; i < 64 * 64; i += 256) {
        int n = i >> 6, q = i & 63;
        int gn = node0 + n;
        float4 v = make_float4(0.f, 0.f, 0.f, 0.f);
        if (gn < NODES) {
            v = (q < 32) ? ((const float4*)(g_agg1 + (size_t)gn * DIN))[q]
                         : ((const float4*)(x      + (size_t)gn * DIN))[q - 32];
        }
        int base = n * SA_STRIDE + q * 4;
        float f[4] = {v.x, v.y, v.z, v.w};
#pragma unroll
        for (int j = 0; j < 4; j++) {
            __nv_bfloat16 h = __float2bfloat16(f[j]);
            sah[base + j] = h;
            sal[base + j] = __float2bfloat16(f[j] - __bfloat162float(h));
        }
    }

    const int w = tid >> 5, lane = tid & 31;
    const int wm = w >> 2, wn = w & 3;          // 2 m-warps x 4 n-warps
    const int r = lane >> 2, c = lane & 3;

    float acc[2][8][4];
#pragma unroll
    for (int a = 0; a < 2; a++)
#pragma unroll
        for (int b = 0; b < 8; b++)
#pragma unroll
            for (int d = 0; d < 4; d++) acc[a][b][d] = 0.f;

    for (int kc = 0; kc < 256; kc += 32) {
        __syncthreads();
        // ---- stage B chunk transposed to [n][kk], hi/lo split ----
        for (int i = tid; i < 32 * 256; i += 256) {
            int kk = i >> 8, n = i & 255;
            int k = kc + kk;
            float wv = (k < 128) ? W1l[(size_t)k * 256 + n]
                                 : W1r[(size_t)(k - 128) * 256 + n];
            __nv_bfloat16 h = __float2bfloat16(wv);
            sbh[n * SB_STRIDE + kk] = h;
            sbl[n * SB_STRIDE + kk] = __float2bfloat16(wv - __bfloat162float(h));
        }
        __syncthreads();

#pragma unroll
        for (int ks = 0; ks < 32; ks += 16) {
            const int k0 = kc + ks;
            uint32_t ah[2][4], al[2][4];
#pragma unroll
            for (int mt = 0; mt < 2; mt++) {
                int e = (wm * 32 + mt * 16 + r) * SA_STRIDE + k0 + 2 * c;
                ah[mt][0] = *(const uint32_t*)(sah + e);
                ah[mt][1] = *(const uint32_t*)(sah + e + 8 * SA_STRIDE);
                ah[mt][2] = *(const uint32_t*)(sah + e + 8);
                ah[mt][3] = *(const uint32_t*)(sah + e + 8 * SA_STRIDE + 8);
                al[mt][0] = *(const uint32_t*)(sal + e);
                al[mt][1] = *(const uint32_t*)(sal + e + 8 * SA_STRIDE);
                al[mt][2] = *(const uint32_t*)(sal + e + 8);
                al[mt][3] = *(const uint32_t*)(sal + e + 8 * SA_STRIDE + 8);
            }
#pragma unroll
            for (int nt = 0; nt < 8; nt++) {
                int e = (wn * 64 + nt * 8 + r) * SB_STRIDE + ks + 2 * c;
                uint32_t bh0 = *(const uint32_t*)(sbh + e);
                uint32_t bh1 = *(const uint32_t*)(sbh + e + 8);
                uint32_t bl0 = *(const uint32_t*)(sbl + e);
                uint32_t bl1 = *(const uint32_t*)(sbl + e + 8);
#pragma unroll
                for (int mt = 0; mt < 2; mt++) {
                    MMA_BF16(acc[mt][nt], ah[mt], bh0, bh1);
                    MMA_BF16(acc[mt][nt], ah[mt], bl0, bl1);
                    MMA_BF16(acc[mt][nt], al[mt], bh0, bh1);
                }
            }
        }
    }

    // ---- epilogue: bias + relu + project onto (u1,u2,v1,v2) ----
#pragma unroll
    for (int mt = 0; mt < 2; mt++) {
#pragma unroll
        for (int hh = 0; hh < 2; hh++) {
            float t1 = 0.f, t2 = 0.f, w1 = 0.f, w2 = 0.f;
#pragma unroll
            for (int nt = 0; nt < 8; nt++) {
                int col = wn * 64 + nt * 8 + 2 * c;
                float2 bb = *(const float2*)(b1l + col);
                float e0 = fmaxf(acc[mt][nt][2 * hh + 0] + bb.x, 0.f);
                float e1 = fmaxf(acc[mt][nt][2 * hh + 1] + bb.y, 0.f);
                float4 p0 = g_P[col], p1 = g_P[col + 1];
                t1 += e0 * p0.x + e1 * p1.x;
                t2 += e0 * p0.y + e1 * p1.y;
                w1 += e0 * p0.z + e1 * p1.z;
                w2 += e0 * p0.w + e1 * p1.w;
            }
#pragma unroll
            for (int off = 1; off <= 2; off <<= 1) {
                t1 += __shfl_xor_sync(0xffffffffu, t1, off);
                t2 += __shfl_xor_sync(0xffffffffu, t2, off);
                w1 += __shfl_xor_sync(0xffffffffu, w1, off);
                w2 += __shfl_xor_sync(0xffffffffu, w2, off);
            }
            if (c == 0) {
                int rl = wm * 32 + mt * 16 + hh * 8 + r;
                spart[wn * 64 + rl] = make_float4(t1, t2, w1, w2);
            }
        }
    }
    __syncthreads();
    if (tid < 64) {
        int gn = node0 + tid;
        if (gn < NODES) {
            float4 s0 = spart[tid],       s1 = spart[64 + tid];
            float4 s2 = spart[128 + tid], s3 = spart[192 + tid];
            g_t12[gn] = make_float2(s0.x + s1.x + s2.x + s3.x,
                                    s0.y + s1.y + s2.y + s3.y);
            g_w12[gn] = make_float2(s0.z + s1.z + s2.z + s3.z,
                                    s0.w + s1.w + s2.w + s3.w);
        }
    }
}

// -------- layer-2 aggregate (gather) + finalize: s = mean(t12) + w + c ------
__global__ void k_fin() {
    int n = blockIdx.x * blockDim.x + threadIdx.x;
    if (n >= NODES) return;
    int start = g_off[n], cnt = g_cnt[n];
    float a1 = 0.f, a2 = 0.f;
    for (int j = 0; j < cnt; j++) {
        float2 t = g_t12[g_csrc[start + j]];
        a1 += t.x; a2 += t.y;
    }
    float r = 1.0f / fmaxf((float)cnt, 1.0f);
    float2 w = g_w12[n];
    g_s[n] = make_float2(a1 * r + w.x + g_c[0],
                         a2 * r + w.y + g_c[1]);
}

// -------- pair head: sigmoid(s1[i] + s2[j] + blin) --------
__global__ void k_pairs(const int* __restrict__ mask,
                        const float* __restrict__ blin,
                        float* __restrict__ out, int P)
{
    int p = blockIdx.x * blockDim.x + threadIdx.x;
    if (p >= P) return;
    int i = mask[2 * p], j = mask[2 * p + 1];
    float z = g_s[i].x + g_s[j].y + blin[0];
    out[p] = 1.0f / (1.0f + expf(-z));
}

// ---------------- launch ----------------
extern "C" void kernel_launch(void* const* d_in, const int* in_sizes, int n_in,
                              void* d_out, int out_size)
{
    const float* x    = (const float*)d_in[0];
    const int*   ei   = (const int*)d_in[1];
    const int*   mask = (const int*)d_in[2];
    const float* W1l  = (const float*)d_in[3];
    const float* b1l  = (const float*)d_in[4];
    const float* W1r  = (const float*)d_in[5];
    const float* W2l  = (const float*)d_in[6];
    const float* b2l  = (const float*)d_in[7];
    const float* W2r  = (const float*)d_in[8];
    const float* Wlin = (const float*)d_in[9];
    const float* blin = (const float*)d_in[10];
    float* out = (float*)d_out;

    int E = in_sizes[1] / 2;
    int P = in_sizes[2] / 2;
    const int* src = ei;
    const int* dst = ei + E;

    const int SMEM = (2 * 64 * SA_STRIDE + 2 * 256 * SB_STRIDE) * (int)sizeof(__nv_bfloat16)
                   + 4 * 64 * (int)sizeof(float4);   // 112,640 B
    cudaFuncSetAttribute((const void*)k_l1,
                         cudaFuncAttributeMaxDynamicSharedMemorySize, SMEM);

    k_zero<<<(NODES + 255) / 256, 256>>>();
    k_hist<<<(E + 255) / 256, 256>>>(dst, E);
    k_scan<<<1, 1024>>>();
    k_fill<<<(E + 255) / 256, 256>>>(src, dst, E);
    k_prep<<<1, 256>>>(W2l, W2r, Wlin, b2l);
    k_agg1<<<(NODES + 7) / 8, 256>>>(x);
    k_l1<<<(NODES + 63) / 64, 256, SMEM>>>(x, W1l, W1r, b1l);
    k_fin<<<(NODES + 255) / 256, 256>>>();
    k_pairs<<<(P + 255) / 256, 256>>>(mask, blin, out, P);
}